// round 7
// baseline (speedup 1.0000x reference)
#include <cuda_runtime.h>
#include <cuda_bf16.h>

// Problem constants
#define BB 8
#define NPTS 16384
#define NG 512          // NUM_GROUPS
#define GS 32           // GROUP_SIZE
#define UK 512          // UPSCALE_K
#define CTX 256         // CONTEXT
#define R2 0.25f        // RADIUS^2

// Output layout (float32, flattened concat of the reference tuple)
#define OFF_GROUPS   0          // 8*256*32*4 = 262144
#define OFF_CENTERS  262144     // 8*256*4   = 8192
#define OFF_EMASK    270336     // 8*256     = 2048
#define OFF_PMASK    272384     // 8*256*32  = 65536

// ---------------- device scratch (no allocations allowed) ----------------
__device__ float4             g_centers[BB * NG];
__device__ unsigned long long g_cand[(size_t)BB * NG * UK];       // 16MB candidate keys
__device__ int                g_cand_cnt[BB * NG];
__device__ int                g_group_len[BB];

// exact (no fma contraction) squared distance, reduce order ((dx^2+dy^2)+dz^2)
__device__ __forceinline__ float d2_exact(float dx, float dy, float dz) {
    return __fadd_rn(__fadd_rn(__fmul_rn(dx, dx), __fmul_rn(dy, dy)), __fmul_rn(dz, dz));
}

__device__ __forceinline__ unsigned encf(float f) {       // order-preserving float->u32
    unsigned u = __float_as_uint(f);
    return (u & 0x80000000u) ? ~u : (u | 0x80000000u);
}
__device__ __forceinline__ unsigned redux_max_u32(unsigned v) {
    unsigned r; asm("redux.sync.max.u32 %0, %1, 0xffffffff;" : "=r"(r) : "r"(v)); return r;
}
__device__ __forceinline__ unsigned redux_min_u32(unsigned v) {
    unsigned r; asm("redux.sync.min.u32 %0, %1, 0xffffffff;" : "=r"(r) : "r"(v)); return r;
}

// packed f32x2 helpers (two independent fp32 RN lanes — bit-exact vs scalar)
#define PACK2(o, lo, hi)  asm("mov.b64 %0, {%1, %2};" : "=l"(o) : "f"(lo), "f"(hi))
#define UNPACK2(lo, hi, i) asm("mov.b64 {%0, %1}, %2;" : "=f"(lo), "=f"(hi) : "l"(i))
#define ADDX2(o, a, b)    asm("add.rn.f32x2 %0, %1, %2;" : "=l"(o) : "l"(a), "l"(b))
#define MULX2(o, a, b)    asm("mul.rn.f32x2 %0, %1, %2;" : "=l"(o) : "l"(a), "l"(b))

// =====================================================================
// K-nop: launch-order shims so ncu's fixed capture point (4th launch)
// lands on fps_kernel.
// =====================================================================
__global__ void nop_kernel() {}

// =====================================================================
// K1: dense FPS, f32x2-packed, single-barrier iterations.
// 1 CTA/batch, 512 threads, 16 point-pairs/thread. x,y in registers,
// z in smem; winner kept in registers by ALL warps (redundant identical
// reduce via 2x redux.sync over the 16 warp keys). Double-buffered key
// array makes ONE __syncthreads per iteration provably sufficient.
// =====================================================================
#define FPS_T 512
#define PAIRS 16
#define FPS_SMEM (NPTS * 8 + NPTS * 4)   // sxy[NPTS] float2 (128KB) + z pairs (64KB)

__global__ void __launch_bounds__(FPS_T, 1)
fps_kernel(const float4* __restrict__ pts, const int* __restrict__ lengths,
           float* __restrict__ out_centers /* d_out + OFF_CENTERS */) {
    extern __shared__ float smem[];
    float2* __restrict__ sxy = (float2*)smem;              // [NPTS] by point
    float2* __restrict__ szp = (float2*)(smem + 2 * NPTS); // [NPTS/2] z pairs
    __shared__ unsigned long long s_wk[2][16];             // double-buffered warp keys
    __shared__ int s_cidx[NG];

    const int b = blockIdx.x, t = threadIdx.x;
    const int wid = t >> 5, lane = t & 31;
    const float4* __restrict__ P = pts + (size_t)b * NPTS;
    const int len = lengths[b];

    unsigned long long X[PAIRS], Y[PAIRS];
    float mind[2 * PAIRS];

#pragma unroll
    for (int i = 0; i < PAIRS; i++) {
        int q = i * FPS_T + t;
        int p0 = 2 * q, p1 = 2 * q + 1;
        float4 v0 = P[p0], v1 = P[p1];
        bool va = (p0 < len), vb = (p1 < len);
        float x0 = va ? v0.x : 1e18f, y0 = va ? v0.y : 1e18f, z0 = va ? v0.z : 1e18f;
        float x1 = vb ? v1.x : 1e18f, y1 = vb ? v1.y : 1e18f, z1 = vb ? v1.z : 1e18f;
        PACK2(X[i], x0, x1);
        PACK2(Y[i], y0, y1);
        sxy[p0] = make_float2(x0, y0);
        sxy[p1] = make_float2(x1, y1);
        szp[q]  = make_float2(z0, z1);
        mind[2 * i]     = va ? 1e10f : -1e30f;
        mind[2 * i + 1] = vb ? 1e10f : -1e30f;
    }
    // winner (index 0) in registers, all threads
    float4 v0 = __ldg(&P[0]);
    float wx = v0.x, wy = v0.y, wz = v0.z;
    if (t == 0) { s_cidx[0] = 0; g_group_len[b] = 0; }
    __syncthreads();

    for (int k = 1; k < NG; k++) {
        unsigned long long nCx, nCy, nCz;
        PACK2(nCx, -wx, -wx);
        PACK2(nCy, -wy, -wy);
        PACK2(nCz, -wz, -wz);

        float fm = -1e30f;
#pragma unroll
        for (int i = 0; i < PAIRS; i++) {
            int q = i * FPS_T + t;
            float2 zz = szp[q];
            unsigned long long Zp, dx, dy, dz, sx, sy, sz, s1, d2p;
            PACK2(Zp, zz.x, zz.y);
            ADDX2(dx, X[i], nCx);           // x - cx  (add of negated, IEEE exact)
            ADDX2(dy, Y[i], nCy);
            ADDX2(dz, Zp,  nCz);
            MULX2(sx, dx, dx);
            MULX2(sy, dy, dy);
            MULX2(sz, dz, dz);
            ADDX2(s1, sx, sy);              // (dx^2 + dy^2)
            ADDX2(d2p, s1, sz);             // ... + dz^2   (same order as scalar)
            float lo, hi;
            UNPACK2(lo, hi, d2p);
            float m0 = fminf(mind[2 * i],     lo);
            float m1 = fminf(mind[2 * i + 1], hi);
            mind[2 * i] = m0; mind[2 * i + 1] = m1;
            fm = fmaxf(fm, fmaxf(m0, m1));
        }

        // warp argmax: max value (redux), min point index among matching lanes
        unsigned ek = encf(fm);
        unsigned wm = redux_max_u32(ek);
        unsigned mybp = 0xFFFFFFFFu;
        if (ek == wm) {                      // predicated rescan (winning lanes only)
#pragma unroll
            for (int i = PAIRS - 1; i >= 0; i--) {
                int q = i * FPS_T + t;
                if (mind[2 * i + 1] == fm) mybp = (unsigned)(2 * q + 1);
                if (mind[2 * i]     == fm) mybp = (unsigned)(2 * q);
            }
        }
        unsigned wi = redux_min_u32(mybp);
        const int par = k & 1;
        if (lane == 0)
            s_wk[par][wid] = ((unsigned long long)wm << 32) | (0xFFFFFFFFu - wi);
        __syncthreads();                     // ONE barrier per iteration

        // every warp redundantly reduces the 16 keys -> identical winner
        unsigned long long kk = (lane < 16) ? s_wk[par][lane] : 0ull;
        unsigned hi = (unsigned)(kk >> 32), lo = (unsigned)kk;
        unsigned mh = redux_max_u32(hi);
        unsigned ml = redux_max_u32((hi == mh) ? lo : 0u);
        int wpt = (int)(0xFFFFFFFFu - ml);
        float2 xy = sxy[wpt];
        float2 z2 = szp[wpt >> 1];
        wx = xy.x; wy = xy.y; wz = (wpt & 1) ? z2.y : z2.x;
        if (t == 0) s_cidx[k] = wpt;
    }
    __syncthreads();

    // tail: gather centers (all 4 channels incl. energy)
    {
        int p = s_cidx[t];
        float4 v = __ldg(&P[p]);
        g_centers[b * NG + t] = v;
        if (t < CTX) ((float4*)out_centers)[b * CTX + t] = v;
    }
}

// =====================================================================
// K2: ball query. Warp owns 4 centers; streams all points (L1/L2-hot),
// ballot+popc gives exact in-index-order candidate rank (first 512 kept).
// Key packs (orderable energy bits << 32) | (0xFFFFFFFF - idx).
// =====================================================================
#define CPW 4
#define BQ_T 256   // 8 warps -> 32 centers per CTA; grid (16, 8)

__global__ __launch_bounds__(BQ_T, 4)
void ballquery_kernel(const float4* __restrict__ pts, const int* __restrict__ lengths) {
    const int b = blockIdx.y;
    const int w = threadIdx.x >> 5, lane = threadIdx.x & 31;
    const int cbase = blockIdx.x * 32 + w * CPW;
    const int len = lengths[b];
    const float4* __restrict__ P = pts + (size_t)b * NPTS;

    float cx[CPW], cy[CPW], cz[CPW];
    int cnt[CPW];
#pragma unroll
    for (int c = 0; c < CPW; c++) {
        float4 cc = g_centers[b * NG + cbase + c];
        cx[c] = cc.x; cy[c] = cc.y; cz[c] = cc.z; cnt[c] = 0;
    }
    unsigned long long* __restrict__ buf = g_cand + (size_t)(b * NG + cbase) * UK;

    const int lim = (len + 31) & ~31;
    const unsigned lt = (1u << lane) - 1u;

    for (int p0 = 0; p0 < lim; p0 += 32) {
        int p = p0 + lane;
        float4 v = __ldg(&P[p]);
        bool inlen = (p < len);
        unsigned eb = __float_as_uint(v.w);
        unsigned ekey = (eb & 0x80000000u) ? ~eb : (eb | 0x80000000u);
        unsigned long long pk = ((unsigned long long)ekey << 32) | (unsigned)(0xFFFFFFFFu - (unsigned)p);

#pragma unroll
        for (int c = 0; c < CPW; c++) {
            if (cnt[c] < UK) {   // warp-uniform
                float dx = v.x - cx[c], dy = v.y - cy[c], dz = v.z - cz[c];
                float d2 = d2_exact(dx, dy, dz);
                bool pred = inlen && (d2 < R2);
                unsigned m = __ballot_sync(0xffffffffu, pred);
                int rnk = cnt[c] + __popc(m & lt);
                if (pred && rnk < UK) buf[(size_t)c * UK + rnk] = pk;
                cnt[c] = min(UK, cnt[c] + __popc(m));
            }
        }
        if (cnt[0] >= UK && cnt[1] >= UK && cnt[2] >= UK && cnt[3] >= UK) break;
    }
    if (lane == 0) {
#pragma unroll
        for (int c = 0; c < CPW; c++) g_cand_cnt[b * NG + cbase + c] = cnt[c];
    }
}

// =====================================================================
// K3: per-group adaptive bitonic (M = next pow2 >= cnt, min 32) descending
// sort of candidate keys, then emit. grid (512, 8), 256 threads.
// =====================================================================
__global__ __launch_bounds__(256, 8)
void sort_emit_kernel(const float4* __restrict__ pts,
                      float* __restrict__ out_groups /* d_out */,
                      float* __restrict__ out_pmask  /* d_out + OFF_PMASK */) {
    const int gi = blockIdx.x;
    const int b  = blockIdx.y;
    const int g  = b * NG + gi;
    const int t  = threadIdx.x;

    __shared__ unsigned long long s[UK];
    const int cnt = g_cand_cnt[g];
    const unsigned long long* __restrict__ src = g_cand + (size_t)g * UK;

    int M = GS;
    while (M < cnt) M <<= 1;                       // 32..512, CTA-uniform

    for (int i = t; i < M; i += 256)
        s[i] = (i < cnt) ? src[i] : 0ull;

    for (int kk = 2; kk <= M; kk <<= 1) {
        for (int j = kk >> 1; j > 0; j >>= 1) {
            __syncthreads();
            for (int e = t; e < M; e += 256) {
                int l = e ^ j;
                if (l > e) {
                    unsigned long long a = s[e], c = s[l];
                    bool dsc = ((e & kk) == 0);
                    bool sw = dsc ? (a < c) : (a > c);
                    if (sw) { s[e] = c; s[l] = a; }
                }
            }
        }
    }
    __syncthreads();

    const int pl = min(cnt, GS);
    if (t == 0 && cnt >= GS) atomicAdd(&g_group_len[b], 1);

    if (gi < CTX) {
        if (t < GS * 4) {
            int slot = t >> 2, ch = t & 3;
            int ss = (slot < pl) ? slot : 0;
            unsigned p = 0xFFFFFFFFu - (unsigned)(s[ss] & 0xFFFFFFFFull);
            const float* pp = (const float*)(pts + ((size_t)b * NPTS + p));
            out_groups[(((size_t)(b * CTX + gi)) * GS + slot) * 4 + ch] = pp[ch];
        } else if (t < GS * 4 + GS) {
            int slot = t - GS * 4;
            out_pmask[(size_t)(b * CTX + gi) * GS + slot] = (slot < pl) ? 1.0f : 0.0f;
        }
    }
}

// =====================================================================
// K4: embedding mask
// =====================================================================
__global__ void emask_kernel(float* __restrict__ em) {
    int b = blockIdx.x, t = threadIdx.x;
    em[b * CTX + t] = (t < g_group_len[b]) ? 1.0f : 0.0f;
}

// =====================================================================
extern "C" void kernel_launch(void* const* d_in, const int* in_sizes, int n_in,
                              void* d_out, int out_size) {
    const float4* pts = (const float4*)d_in[0];   // (8,16384,4) f32
    const int*   lens = (const int*)d_in[1];      // (8,)
    float* out = (float*)d_out;

    cudaFuncSetAttribute(fps_kernel,
                         cudaFuncAttributeMaxDynamicSharedMemorySize, FPS_SMEM);

    // 3 shims so ncu's capture point (4th launch) = fps_kernel
    nop_kernel<<<1, 32>>>();
    nop_kernel<<<1, 32>>>();
    nop_kernel<<<1, 32>>>();
    fps_kernel<<<BB, FPS_T, FPS_SMEM>>>(pts, lens, out + OFF_CENTERS);
    ballquery_kernel<<<dim3(16, BB), BQ_T>>>(pts, lens);
    sort_emit_kernel<<<dim3(NG, BB), 256>>>(pts, out + OFF_GROUPS, out + OFF_PMASK);
    emask_kernel<<<BB, CTX>>>(out + OFF_EMASK);
}